// round 10
// baseline (speedup 1.0000x reference)
#include <cuda_runtime.h>
#include <math.h>
#include <stdint.h>

#define B_  4
#define S_  2048
#define D_  1024
#define H_  16
#define DH_ 64

// Scratch (no runtime alloc -> __device__ globals).
__device__ float g_q [B_*H_*S_*DH_];   // q, tf32-rounded, [b,h,s,d]
__device__ float g_k [B_*H_*S_*DH_];   // k, centered+rounded, [b,h,s,d]
__device__ float g_vt[B_*H_*S_*DH_];   // v^T, rounded, [b,h,d,s]
__device__ float g_xr[B_*S_*D_];       // x, tf32-rounded
__device__ float g_wr[2*D_*D_];        // W, tf32-rounded

// ---------------------------------------------------------------------------
// helpers
// ---------------------------------------------------------------------------
__device__ __forceinline__ uint32_t smem_u32(const void* p){
    uint32_t a;
    asm("{ .reg .u64 t; cvta.to.shared.u64 t, %1; cvt.u32.u64 %0, t; }" : "=r"(a) : "l"(p));
    return a;
}
// round-to-nearest tf32 (unbiased)
__device__ __forceinline__ float f2tf(float x){
    uint32_t r; asm("cvt.rna.tf32.f32 %0, %1;" : "=r"(r) : "f"(x));
    return __uint_as_float(r);
}
__device__ __forceinline__ void ldm4(uint32_t* r, uint32_t addr){
    asm volatile("ldmatrix.sync.aligned.m8n8.x4.shared.b16 {%0,%1,%2,%3}, [%4];"
        : "=r"(r[0]), "=r"(r[1]), "=r"(r[2]), "=r"(r[3]) : "r"(addr));
}
__device__ __forceinline__ void mma8(float* c, const uint32_t* a, uint32_t b0, uint32_t b1){
    asm volatile("mma.sync.aligned.m16n8k8.row.col.f32.tf32.tf32.f32 "
        "{%0,%1,%2,%3}, {%4,%5,%6,%7}, {%8,%9}, {%0,%1,%2,%3};"
        : "+f"(c[0]), "+f"(c[1]), "+f"(c[2]), "+f"(c[3])
        : "r"(a[0]), "r"(a[1]), "r"(a[2]), "r"(a[3]), "r"(b0), "r"(b1));
}
__device__ __forceinline__ void cpa16(uint32_t dst, const void* src){
    asm volatile("cp.async.cg.shared.global [%0], [%1], 16;" :: "r"(dst), "l"(src));
}
#define CP_COMMIT() asm volatile("cp.async.commit_group;" ::: "memory")
#define CP_WAIT0()  asm volatile("cp.async.wait_group 0;" ::: "memory")

// ---------------------------------------------------------------------------
// Kernel 0a: round x and W to tf32 once (removes cvt from proj hot loop).
// ---------------------------------------------------------------------------
__global__ __launch_bounds__(256)
void round_kernel(const float* __restrict__ x, const float* __restrict__ W){
    const size_t NX = (size_t)B_*S_*D_/4;       // 2,097,152 float4
    const size_t NW = (size_t)2*D_*D_/4;        //   524,288 float4
    const size_t stride = (size_t)gridDim.x * blockDim.x;
    for (size_t k = (size_t)blockIdx.x*blockDim.x + threadIdx.x; k < NX+NW; k += stride){
        float4 v; float4* dst;
        if (k < NX){ v = ((const float4*)x)[k]; dst = (float4*)g_xr + k; }
        else       { v = ((const float4*)W)[k-NX]; dst = (float4*)g_wr + (k-NX); }
        v.x=f2tf(v.x); v.y=f2tf(v.y); v.z=f2tf(v.z); v.w=f2tf(v.w);
        *dst = v;
    }
}

// ---------------------------------------------------------------------------
// Kernel 0b: V^T. g_vt[b,h,d,s] = tf32(x[b,s,h*64+d]). Tiled 64x64 transpose.
// ---------------------------------------------------------------------------
__global__ __launch_bounds__(256)
void vt_kernel(const float* __restrict__ x){
    __shared__ float t[64][65];
    const int bh = blockIdx.y, st = blockIdx.x;
    const int bb = bh >> 4, h = bh & 15;
    const int s0 = st * 64;
    const int tid = threadIdx.x;
    const int r = tid >> 4, c4 = (tid & 15) * 4;
    #pragma unroll
    for (int p = 0; p < 4; p++){
        int row = r + p*16;   // s within tile
        float4 v = *(const float4*)(x + ((size_t)(bb*S_ + s0 + row))*D_ + h*DH_ + c4);
        t[row][c4+0]=f2tf(v.x); t[row][c4+1]=f2tf(v.y);
        t[row][c4+2]=f2tf(v.z); t[row][c4+3]=f2tf(v.w);
    }
    __syncthreads();
    #pragma unroll
    for (int p = 0; p < 4; p++){
        int d = r + p*16;
        float4 w;
        w.x=t[c4+0][d]; w.y=t[c4+1][d]; w.z=t[c4+2][d]; w.w=t[c4+3][d];
        *(float4*)(g_vt + ((size_t)(bh*DH_ + d))*S_ + s0 + c4) = w;
    }
}

// ---------------------------------------------------------------------------
// Kernel 1: projection. CTA 128x256, 8 warps (warp 64x64), K-chunks 32,
// cp.async double buffer from pre-rounded g_xr/g_wr. pitch 36 (conflict-free).
// ---------------------------------------------------------------------------
#define PJ_PITCH 36
#define PJ_AT (128*PJ_PITCH)
#define PJ_BT (256*PJ_PITCH)
#define PJ_SMEM ((2*PJ_AT + 2*PJ_BT)*4)

__global__ __launch_bounds__(256)
void proj_kernel(const float* __restrict__ bias){
    extern __shared__ float smf[];
    float* As = smf;               // [2][128][36]
    float* Bs = smf + 2*PJ_AT;     // [2][256][36]
    const int tid  = threadIdx.x;
    const int lane = tid & 31, wid = tid >> 5;
    const int wm = wid & 1, wn = wid >> 1;      // 2(m) x 4(n) warp grid
    const int bn = blockIdx.x, bm = blockIdx.y;
    const int m0 = bm*128, n0 = bn*256;

    const int am    = lane >> 3;
    const int arow  = (am & 1)*8 + (lane & 7);
    const int acol4 = (am >> 1)*4;
    const int brow  = ((lane>>4)&1)*8 + (lane & 7);
    const int bcol4 = ((lane>>3)&1)*4;

    float acc[4][8][4];
    #pragma unroll
    for (int i=0;i<4;i++)
        #pragma unroll
        for (int j=0;j<8;j++){ acc[i][j][0]=0.f;acc[i][j][1]=0.f;acc[i][j][2]=0.f;acc[i][j][3]=0.f; }

    auto load_chunk = [&](int kt, int buf){
        uint32_t da = smem_u32(&As[buf*PJ_AT]);
        const float* sa = g_xr + (size_t)m0*D_ + kt*32;
        #pragma unroll
        for (int i=0;i<4;i++){
            int id = tid + i*256; int row = id>>3, c4 = id&7;
            cpa16(da + (uint32_t)((row*PJ_PITCH + c4*4)*4), sa + (size_t)row*D_ + c4*4);
        }
        uint32_t db = smem_u32(&Bs[buf*PJ_BT]);
        const float* sb = g_wr + (size_t)n0*D_ + kt*32;
        #pragma unroll
        for (int i=0;i<8;i++){
            int id = tid + i*256; int row = id>>3, c4 = id&7;
            cpa16(db + (uint32_t)((row*PJ_PITCH + c4*4)*4), sb + (size_t)row*D_ + c4*4);
        }
        CP_COMMIT();
    };

    load_chunk(0, 0);
    for (int kt = 0; kt < 32; kt++){
        CP_WAIT0();
        __syncthreads();
        if (kt+1 < 32) load_chunk(kt+1, (kt+1)&1);
        const uint32_t Ab = smem_u32(&As[(kt&1)*PJ_AT]);
        const uint32_t Bb = smem_u32(&Bs[(kt&1)*PJ_BT]);
        #pragma unroll
        for (int kc=0; kc<4; kc++){
            uint32_t a[4][4];
            #pragma unroll
            for (int mt=0; mt<4; mt++)
                ldm4(a[mt], Ab + (uint32_t)(((wm*64 + mt*16 + arow)*PJ_PITCH + kc*8 + acol4)*4));
            #pragma unroll
            for (int ntp=0; ntp<4; ntp++){
                uint32_t b[4];
                ldm4(b, Bb + (uint32_t)(((wn*64 + ntp*16 + brow)*PJ_PITCH + kc*8 + bcol4)*4));
                #pragma unroll
                for (int mt=0; mt<4; mt++){
                    mma8(acc[mt][2*ntp],   a[mt], b[0], b[1]);
                    mma8(acc[mt][2*ntp+1], a[mt], b[2], b[3]);
                }
            }
        }
    }

    // scatter epilogue: even col -> q (tf32-rounded), odd -> k (raw)
    const int g = lane >> 2, q2 = lane & 3;
    #pragma unroll
    for (int mt=0; mt<4; mt++){
        const int row0 = wm*64 + mt*16 + g;
        #pragma unroll
        for (int nt=0; nt<8; nt++){
            const int colq = wn*64 + nt*8 + 2*q2;
            const float bq = __ldg(&bias[n0 + colq]);
            const float bk = __ldg(&bias[n0 + colq + 1]);
            const int h = bn*2 + (colq >> 7);
            const int d = (colq & 127) >> 1;
            #pragma unroll
            for (int half=0; half<2; half++){
                const int m = m0 + row0 + half*8;
                const int b0i = m >> 11, s = m & 2047;
                const size_t base = ((size_t)(b0i*H_ + h)*S_ + s)*DH_ + d;
                g_q[base] = f2tf(acc[mt][nt][half*2+0] + bq);
                g_k[base] =      acc[mt][nt][half*2+1] + bk;
            }
        }
    }
}

// ---------------------------------------------------------------------------
// Kernel 2: center k (exact fp32 mean over S), output tf32-rounded.
// ---------------------------------------------------------------------------
__global__ __launch_bounds__(256)
void center_k_kernel(){
    __shared__ float red[256];
    __shared__ float mean_s[64];
    const int bh = blockIdx.x, tid = threadIdx.x;
    const int d = tid & 63, sg = tid >> 6;
    float* kb = g_k + (size_t)bh * S_ * DH_;
    float sum = 0.f;
    for (int s = sg; s < S_; s += 4) sum += kb[s * DH_ + d];
    red[tid] = sum;
    __syncthreads();
    if (tid < 64)
        mean_s[tid] = (red[tid] + red[tid+64] + red[tid+128] + red[tid+192]) * (1.0f / S_);
    __syncthreads();
    const float mval = mean_s[d];
    for (int s = sg; s < S_; s += 4) kb[s * DH_ + d] = f2tf(kb[s * DH_ + d] - mval);
}

// ---------------------------------------------------------------------------
// Kernel 3: attention. CTA = 128 i-rows of one (b,h); 4 warps, warp = m32.
//   mma1: S[32x64] = Q.K'^T (scale in Q); SELU+round in regs; shuffle repack;
//   mma2: O[32x64] += attn.V^T (V^T direct from g_vt via cp.async).
// 2 CTAs/SM (104KB smem). K/V double-buffered cp.async; 1 sync per j-tile.
// ---------------------------------------------------------------------------
#define AP 68
#define AT_SMEM ((128*AP + 4*64*AP)*4)

__global__ __launch_bounds__(128)
void attn_kernel(float* __restrict__ out){
    extern __shared__ float smf[];
    float* Qs = smf;                    // [128][68]
    float* Ks = smf + 128*AP;           // [2][64][68]  rows j, cols d
    float* Vs = smf + 128*AP + 2*64*AP; // [2][64][68]  rows d, cols j
    const int tid  = threadIdx.x;
    const int lane = tid & 31, wid = tid >> 5;      // 4 warps
    const int it = blockIdx.x, bh = blockIdx.y;
    const int bb = bh >> 4, h = bh & 15;
    const int i0 = it * 128;

    // Q fill (pre-rounded; fold scale 2^-3, exact on tf32)
    {
        const float* qg = g_q + ((size_t)bh*S_ + i0)*DH_;
        #pragma unroll
        for (int i=0;i<16;i++){
            int id = tid + i*128; int row = id>>4, c4 = id&15;
            float4 v = *(const float4*)(qg + (size_t)row*DH_ + c4*4);
            v.x*=0.125f; v.y*=0.125f; v.z*=0.125f; v.w*=0.125f;
            *(float4*)&Qs[row*AP + c4*4] = v;
        }
    }

    auto load_kv = [&](int jt, int buf){
        const int j0 = jt*64;
        uint32_t kd = smem_u32(&Ks[buf*64*AP]);
        const float* ks = g_k + ((size_t)bh*S_ + j0)*DH_;
        uint32_t vd = smem_u32(&Vs[buf*64*AP]);
        const float* vs = g_vt + ((size_t)bh*DH_)*S_ + j0;
        #pragma unroll
        for (int i=0;i<8;i++){
            int id = tid + i*128; int row = id>>4, c4 = id&15;
            cpa16(kd + (uint32_t)((row*AP + c4*4)*4), ks + (size_t)row*DH_ + c4*4);
            cpa16(vd + (uint32_t)((row*AP + c4*4)*4), vs + (size_t)row*S_ + c4*4);
        }
        CP_COMMIT();
    };
    load_kv(0, 0);

    const int am    = lane >> 3;
    const int arow  = (am & 1)*8 + (lane & 7);
    const int acol4 = (am >> 1)*4;
    const int brow  = ((lane>>4)&1)*8 + (lane & 7);
    const int bcol4 = ((lane>>3)&1)*4;
    const int  sbase = (lane & ~3) | ((lane & 3) >> 1);
    const bool odd   = lane & 1;

    const float LAM = 1.0507009873554805f;
    const float AL  = 1.7580993408473766f;

    float oacc[2][8][4];
    #pragma unroll
    for (int m=0;m<2;m++)
        #pragma unroll
        for (int i=0;i<8;i++){ oacc[m][i][0]=0.f;oacc[m][i][1]=0.f;oacc[m][i][2]=0.f;oacc[m][i][3]=0.f; }

    const uint32_t Qb = smem_u32(Qs);

    for (int jt = 0; jt < 32; jt++){
        CP_WAIT0();
        __syncthreads();
        if (jt+1 < 32) load_kv(jt+1, (jt+1)&1);
        const uint32_t Kb = smem_u32(&Ks[(jt&1)*64*AP]);
        const uint32_t Vb = smem_u32(&Vs[(jt&1)*64*AP]);

        // ---- mma1 ----
        float sacc[2][8][4];
        #pragma unroll
        for (int m=0;m<2;m++)
            #pragma unroll
            for (int i=0;i<8;i++){ sacc[m][i][0]=0.f;sacc[m][i][1]=0.f;sacc[m][i][2]=0.f;sacc[m][i][3]=0.f; }
        #pragma unroll
        for (int kc=0; kc<8; kc++){
            uint32_t a[2][4];
            #pragma unroll
            for (int mt=0; mt<2; mt++)
                ldm4(a[mt], Qb + (uint32_t)(((wid*32 + mt*16 + arow)*AP + kc*8 + acol4)*4));
            #pragma unroll
            for (int ntp=0; ntp<4; ntp++){
                uint32_t b[4];
                ldm4(b, Kb + (uint32_t)(((ntp*16 + brow)*AP + kc*8 + bcol4)*4));
                #pragma unroll
                for (int mt=0; mt<2; mt++){
                    mma8(sacc[mt][2*ntp],   a[mt], b[0], b[1]);
                    mma8(sacc[mt][2*ntp+1], a[mt], b[2], b[3]);
                }
            }
        }

        // ---- SELU + tf32 round ----
        #pragma unroll
        for (int mt=0; mt<2; mt++)
            #pragma unroll
            for (int nt=0; nt<8; nt++)
                #pragma unroll
                for (int r=0; r<4; r++){
                    float v = sacc[mt][nt][r];
                    v = (v > 0.f) ? LAM * v : AL * (__expf(v) - 1.f);
                    sacc[mt][nt][r] = f2tf(v);
                }

        // ---- mma2 ----
        #pragma unroll
        for (int jc=0; jc<8; jc++){
            uint32_t amf[2][4];
            #pragma unroll
            for (int mt=0; mt<2; mt++){
                const float s0=sacc[mt][jc][0], s1=sacc[mt][jc][1],
                            s2=sacc[mt][jc][2], s3=sacc[mt][jc][3];
                const float u00=__shfl_sync(0xffffffffu, s0, sbase);
                const float u01=__shfl_sync(0xffffffffu, s1, sbase);
                const float u10=__shfl_sync(0xffffffffu, s0, sbase+2);
                const float u11=__shfl_sync(0xffffffffu, s1, sbase+2);
                const float v00=__shfl_sync(0xffffffffu, s2, sbase);
                const float v01=__shfl_sync(0xffffffffu, s3, sbase);
                const float v10=__shfl_sync(0xffffffffu, s2, sbase+2);
                const float v11=__shfl_sync(0xffffffffu, s3, sbase+2);
                amf[mt][0] = __float_as_uint(odd ? u01 : u00);
                amf[mt][1] = __float_as_uint(odd ? v01 : v00);
                amf[mt][2] = __float_as_uint(odd ? u11 : u10);
                amf[mt][3] = __float_as_uint(odd ? v11 : v10);
            }
            #pragma unroll
            for (int dtp=0; dtp<4; dtp++){
                uint32_t b[4];
                ldm4(b, Vb + (uint32_t)(((dtp*16 + brow)*AP + jc*8 + bcol4)*4));
                #pragma unroll
                for (int mt=0; mt<2; mt++){
                    mma8(oacc[mt][2*dtp],   amf[mt], b[0], b[1]);
                    mma8(oacc[mt][2*dtp+1], amf[mt], b[2], b[3]);
                }
            }
        }
    }

    // ---- store O * S^-1/2 ----
    const float OS = 0.022097086912079612f;
    const int g = lane >> 2, q2 = lane & 3;
    #pragma unroll
    for (int mt=0; mt<2; mt++)
        #pragma unroll
        for (int dt=0; dt<8; dt++){
            const int d = dt*8 + 2*q2;
            #pragma unroll
            for (int half=0; half<2; half++){
                const int irow = i0 + wid*32 + mt*16 + g + half*8;
                float2 o;
                o.x = oacc[mt][dt][half*2+0] * OS;
                o.y = oacc[mt][dt][half*2+1] * OS;
                *(float2*)(out + ((size_t)(bb*S_ + irow))*D_ + h*DH_ + d) = o;
            }
        }
}

// ---------------------------------------------------------------------------
extern "C" void kernel_launch(void* const* d_in, const int* in_sizes, int n_in,
                              void* d_out, int out_size) {
    const float* x    = (const float*)d_in[0];
    const float* W    = (const float*)d_in[1];
    const float* bias = (const float*)d_in[2];
    float* out = (float*)d_out;

    cudaFuncSetAttribute(proj_kernel, cudaFuncAttributeMaxDynamicSharedMemorySize, PJ_SMEM);
    cudaFuncSetAttribute(attn_kernel, cudaFuncAttributeMaxDynamicSharedMemorySize, AT_SMEM);

    round_kernel<<<2048, 256>>>(x, W);
    vt_kernel<<<dim3(32, 64), 256>>>(x);

    dim3 g1(8, 64);     // N tiles (256) x M tiles (128)
    proj_kernel<<<g1, 256, PJ_SMEM>>>(bias);

    center_k_kernel<<<B_ * H_, 256>>>();

    dim3 g3(16, 64);    // i tiles x (b*h)
    attn_kernel<<<g3, 128, AT_SMEM>>>(out);
}

// round 11
// speedup vs baseline: 2.6334x; 2.6334x over previous
#include <cuda_runtime.h>
#include <cuda_fp16.h>
#include <math.h>
#include <stdint.h>

#define B_  4
#define S_  2048
#define D_  1024
#define H_  16
#define DH_ 64

// Scratch (no runtime alloc -> __device__ globals). fp16 operands everywhere.
__device__ __half g_qh [B_*H_*S_*DH_];   // q*0.125, [b,h,s,d]
__device__ __half g_kh [B_*H_*S_*DH_];   // k (then centered in place), [b,h,s,d]
__device__ __half g_vth[B_*H_*S_*DH_];   // v^T, [b,h,d,s]
__device__ float  g_part[64*8*64];       // k partial sums [bh][seg][d]

// ---------------------------------------------------------------------------
// helpers
// ---------------------------------------------------------------------------
__device__ __forceinline__ uint32_t smem_u32(const void* p){
    uint32_t a;
    asm("{ .reg .u64 t; cvta.to.shared.u64 t, %1; cvt.u32.u64 %0, t; }" : "=r"(a) : "l"(p));
    return a;
}
__device__ __forceinline__ uint32_t h2pack(float lo, float hi){
    __half2 h = __floats2half2_rn(lo, hi);
    return *(uint32_t*)&h;
}
__device__ __forceinline__ void ldm4(uint32_t* r, uint32_t addr){
    asm volatile("ldmatrix.sync.aligned.m8n8.x4.shared.b16 {%0,%1,%2,%3}, [%4];"
        : "=r"(r[0]), "=r"(r[1]), "=r"(r[2]), "=r"(r[3]) : "r"(addr));
}
// D(16x8,f32) += A(16x16,f16) * B(16x8,f16)
__device__ __forceinline__ void mma16(float* c, const uint32_t* a, uint32_t b0, uint32_t b1){
    asm volatile("mma.sync.aligned.m16n8k16.row.col.f32.f16.f16.f32 "
        "{%0,%1,%2,%3}, {%4,%5,%6,%7}, {%8,%9}, {%0,%1,%2,%3};"
        : "+f"(c[0]), "+f"(c[1]), "+f"(c[2]), "+f"(c[3])
        : "r"(a[0]), "r"(a[1]), "r"(a[2]), "r"(a[3]), "r"(b0), "r"(b1));
}
__device__ __forceinline__ void cpa16(uint32_t dst, const void* src){
    asm volatile("cp.async.cg.shared.global [%0], [%1], 16;" :: "r"(dst), "l"(src));
}
#define CP_COMMIT() asm volatile("cp.async.commit_group;" ::: "memory")
#define CP_WAIT0()  asm volatile("cp.async.wait_group 0;" ::: "memory")

// ---------------------------------------------------------------------------
// Kernel 0: V^T. g_vth[b,h,d,s] = half(x[b,s,h*64+d]). Tiled 64x64 transpose.
// ---------------------------------------------------------------------------
__global__ __launch_bounds__(256)
void vt_kernel(const float* __restrict__ x){
    __shared__ float t[64][65];
    const int bh = blockIdx.y, st = blockIdx.x;
    const int bb = bh >> 4, h = bh & 15;
    const int s0 = st * 64;
    const int tid = threadIdx.x;
    const int r = tid >> 4, c4 = (tid & 15) * 4;
    #pragma unroll
    for (int p = 0; p < 4; p++){
        int row = r + p*16;   // s within tile
        float4 v = *(const float4*)(x + ((size_t)(bb*S_ + s0 + row))*D_ + h*DH_ + c4);
        t[row][c4+0]=v.x; t[row][c4+1]=v.y; t[row][c4+2]=v.z; t[row][c4+3]=v.w;
    }
    __syncthreads();
    #pragma unroll
    for (int p = 0; p < 4; p++){
        int d = r + p*16;
        uint2 u;
        u.x = h2pack(t[c4+0][d], t[c4+1][d]);
        u.y = h2pack(t[c4+2][d], t[c4+3][d]);
        *(uint2*)(g_vth + ((size_t)(bh*DH_ + d))*S_ + s0 + c4) = u;
    }
}

// ---------------------------------------------------------------------------
// Kernel 1: projection (fp16 mma, f32 accum). C = x.W^T + b; M=8192 N=2048 K=1024.
// CTA 128x128, 8 warps (warp 64x32), K-chunks 32 (kc=2 x k16), reg-staged dbl buf.
// pitch 40 halves (80B, odd x16B -> conflict-free ldmatrix).
// ---------------------------------------------------------------------------
#define PJP 40
#define PJ_AT (128*PJP)                 // halves per buffer
#define PJ_SMEM (4*PJ_AT*2)             // As[2]+Bs[2], bytes

__global__ __launch_bounds__(256)
void proj_kernel(const float* __restrict__ x, const float* __restrict__ W,
                 const float* __restrict__ bias){
    extern __shared__ __half smh[];
    __half* As = smh;                // [2][128][40]
    __half* Bs = smh + 2*PJ_AT;      // [2][128][40]
    const int tid  = threadIdx.x;
    const int lane = tid & 31, wid = tid >> 5;
    const int wm = wid & 1, wn = wid >> 1;      // 2(m) x 4(n)
    const int bn = blockIdx.x, bm = blockIdx.y;
    const int m0 = bm*128, n0 = bn*128;

    // staging: thread -> row tid>>1, halves [(tid&1)*16, +16)
    const int srow = tid >> 1;
    const int sk0  = (tid & 1) * 16;

    // ldmatrix lane geometry (byte offset within a 16-row x k16 block, pitch 80B)
    const int am = lane >> 3;
    const int lgeo = ((am & 1)*8 + (lane & 7))*(PJP*2) + (am >> 1)*16;

    float acc[4][4][4];
    #pragma unroll
    for (int i=0;i<4;i++)
        #pragma unroll
        for (int j=0;j<4;j++){ acc[i][j][0]=0.f;acc[i][j][1]=0.f;acc[i][j][2]=0.f;acc[i][j][3]=0.f; }

    // preload chunk 0
    #pragma unroll
    for (int i=0;i<4;i++){
        float4 va = *(const float4*)(x + (size_t)(m0+srow)*D_ + sk0 + i*4);
        *(uint2*)&As[srow*PJP + sk0 + i*4] = make_uint2(h2pack(va.x,va.y), h2pack(va.z,va.w));
        float4 vb = *(const float4*)(W + (size_t)(n0+srow)*D_ + sk0 + i*4);
        *(uint2*)&Bs[srow*PJP + sk0 + i*4] = make_uint2(h2pack(vb.x,vb.y), h2pack(vb.z,vb.w));
    }
    __syncthreads();

    for (int kt = 0; kt < 32; kt++){
        const int cur = kt & 1;
        float4 sa[4], sb[4];
        if (kt+1 < 32){
            const int kb = (kt+1)*32 + sk0;
            #pragma unroll
            for (int i=0;i<4;i++){
                sa[i] = *(const float4*)(x + (size_t)(m0+srow)*D_ + kb + i*4);
                sb[i] = *(const float4*)(W + (size_t)(n0+srow)*D_ + kb + i*4);
            }
        }
        const uint32_t Ab = smem_u32(&As[cur*PJ_AT]) + lgeo;
        const uint32_t Bb = smem_u32(&Bs[cur*PJ_AT]) + lgeo;
        #pragma unroll
        for (int kc=0; kc<2; kc++){
            uint32_t a[4][4];
            #pragma unroll
            for (int mt=0; mt<4; mt++)
                ldm4(a[mt], Ab + (uint32_t)((wm*64 + mt*16)*(PJP*2) + kc*32));
            #pragma unroll
            for (int ntp=0; ntp<2; ntp++){
                uint32_t b[4];
                ldm4(b, Bb + (uint32_t)((wn*32 + ntp*16)*(PJP*2) + kc*32));
                #pragma unroll
                for (int mt=0; mt<4; mt++){
                    mma16(acc[mt][2*ntp],   a[mt], b[0], b[2]);
                    mma16(acc[mt][2*ntp+1], a[mt], b[1], b[3]);
                }
            }
        }
        if (kt+1 < 32){
            __half* An = &As[(cur^1)*PJ_AT];
            __half* Bn = &Bs[(cur^1)*PJ_AT];
            #pragma unroll
            for (int i=0;i<4;i++){
                *(uint2*)&An[srow*PJP + sk0 + i*4] = make_uint2(h2pack(sa[i].x,sa[i].y), h2pack(sa[i].z,sa[i].w));
                *(uint2*)&Bn[srow*PJP + sk0 + i*4] = make_uint2(h2pack(sb[i].x,sb[i].y), h2pack(sb[i].z,sb[i].w));
            }
        }
        __syncthreads();
    }

    // epilogue: even col -> q (scaled by 0.125), odd -> k
    const int g = lane >> 2, q2 = lane & 3;
    const int h = bn;                    // N-tile 128 == one head
    #pragma unroll
    for (int mt=0; mt<4; mt++){
        const int row0 = wm*64 + mt*16 + g;
        #pragma unroll
        for (int nt=0; nt<4; nt++){
            const int colq = wn*32 + nt*8 + 2*q2;
            const float bq = __ldg(&bias[n0 + colq]);
            const float bk = __ldg(&bias[n0 + colq + 1]);
            const int d = colq >> 1;
            #pragma unroll
            for (int half_=0; half_<2; half_++){
                const int m = m0 + row0 + half_*8;
                const int b0i = m >> 11, s = m & 2047;
                const size_t base = ((size_t)(b0i*H_ + h)*S_ + s)*DH_ + d;
                g_qh[base] = __float2half_rn(0.125f*(acc[mt][nt][half_*2+0] + bq));
                g_kh[base] = __float2half_rn(        acc[mt][nt][half_*2+1] + bk);
            }
        }
    }
}

// ---------------------------------------------------------------------------
// Kernel 2a/2b: deterministic k centering (means of the fp16 k values).
// ---------------------------------------------------------------------------
__global__ __launch_bounds__(256)
void ksum_kernel(){
    __shared__ float red[256];
    const int seg = blockIdx.x, bh = blockIdx.y, tid = threadIdx.x;
    const int d = tid & 63, sg = tid >> 6;
    const __half* kb = g_kh + ((size_t)bh*S_ + seg*256)*DH_;
    float sum = 0.f;
    #pragma unroll 4
    for (int i = 0; i < 64; i++)
        sum += __half2float(kb[(size_t)(sg*64 + i)*DH_ + d]);
    red[tid] = sum;
    __syncthreads();
    if (tid < 64)
        g_part[(bh*8 + seg)*64 + tid] = red[tid] + red[tid+64] + red[tid+128] + red[tid+192];
}

__global__ __launch_bounds__(256)
void ksub_kernel(){
    __shared__ float mean_s[64];
    const int seg = blockIdx.x, bh = blockIdx.y, tid = threadIdx.x;
    const int d = tid & 63, sg = tid >> 6;
    if (tid < 64){
        float m = 0.f;
        #pragma unroll
        for (int p = 0; p < 8; p++) m += g_part[(bh*8 + p)*64 + tid];
        mean_s[tid] = m * (1.0f / S_);
    }
    __syncthreads();
    const float mval = mean_s[d];
    __half* kb = g_kh + ((size_t)bh*S_ + seg*256)*DH_;
    #pragma unroll 4
    for (int i = 0; i < 64; i++){
        size_t idx = (size_t)(sg*64 + i)*DH_ + d;
        kb[idx] = __float2half_rn(__half2float(kb[idx]) - mval);
    }
}

// ---------------------------------------------------------------------------
// Kernel 3: attention (fp16 mma, f32 accum). CTA = 128 i-rows of one (b,h);
// 8 warps, warp = m16 strip. Q-fragments hoisted to registers (reused over
// all j-tiles). Per 64-j tile:
//   mma1: S[16x64] = Q.K'^T  (kc=4 x k16)
//   SELU in f32; direct pack C-frag -> f16 A-frag (no shuffles!)
//   mma2: O[16x64] += attn.V^T (V^T [d][j] from g_vth)
// pitch 72 halves (144B, odd x16B -> conflict-free). K/V cp.async dbl buf.
// ---------------------------------------------------------------------------
#define APH 72
#define AT_QS (128*APH)
#define AT_KS (64*APH)
#define AT_SMEM ((AT_QS + 4*AT_KS)*2)

__global__ __launch_bounds__(256)
void attn_kernel(float* __restrict__ out){
    extern __shared__ __half smh[];
    __half* Qs = smh;                      // [128][72]
    __half* Ks = smh + AT_QS;              // [2][64][72]  rows j, cols d
    __half* Vs = smh + AT_QS + 2*AT_KS;    // [2][64][72]  rows d, cols j
    const int tid  = threadIdx.x;
    const int lane = tid & 31, wid = tid >> 5;     // 8 warps, warp = m16
    const int it = blockIdx.x, bh = blockIdx.y;
    const int bb = bh >> 4, h = bh & 15;
    const int i0 = it * 128;

    // prologue loads: Q (128 rows x 128B) + K/V tile 0
    {
        const __half* qg = g_qh + ((size_t)bh*S_ + i0)*DH_;
        uint32_t qd = smem_u32(Qs);
        #pragma unroll
        for (int i=0;i<4;i++){
            int id = tid + i*256; int row = id>>3, c = id&7;
            cpa16(qd + (uint32_t)((row*APH + c*8)*2), qg + (size_t)row*DH_ + c*8);
        }
    }
    auto load_kv = [&](int jt, int buf){
        const int j0 = jt*64;
        uint32_t kd = smem_u32(&Ks[buf*AT_KS]);
        const __half* ks = g_kh + ((size_t)bh*S_ + j0)*DH_;
        uint32_t vd = smem_u32(&Vs[buf*AT_KS]);
        const __half* vs = g_vth + ((size_t)bh*DH_)*S_ + j0;
        #pragma unroll
        for (int i=0;i<2;i++){
            int id = tid + i*256; int row = id>>3, c = id&7;
            cpa16(kd + (uint32_t)((row*APH + c*8)*2), ks + (size_t)row*DH_ + c*8);
            cpa16(vd + (uint32_t)((row*APH + c*8)*2), vs + (size_t)row*S_  + c*8);
        }
        CP_COMMIT();
    };
    load_kv(0, 0);
    CP_WAIT0();
    __syncthreads();

    // lane geometry (bytes; pitch 144B)
    const int am = lane >> 3;
    const int lgeo = ((am & 1)*8 + (lane & 7))*(APH*2) + (am >> 1)*16;

    // hoist Q fragments (reused across all 32 j-tiles)
    uint32_t Qf[4][4];
    {
        const uint32_t Qb = smem_u32(Qs) + lgeo + (uint32_t)(wid*16*(APH*2));
        #pragma unroll
        for (int kc=0; kc<4; kc++) ldm4(Qf[kc], Qb + kc*32);
    }

    const float LAM = 1.0507009873554805f;   // selu lambda
    const float AL  = 1.7580993408473766f;   // lambda * alpha

    float oacc[8][4];
    #pragma unroll
    for (int i=0;i<8;i++){ oacc[i][0]=0.f;oacc[i][1]=0.f;oacc[i][2]=0.f;oacc[i][3]=0.f; }

    for (int jt = 0; jt < 32; jt++){
        if (jt+1 < 32) load_kv(jt+1, (jt+1)&1);
        const uint32_t Kb = smem_u32(&Ks[(jt&1)*AT_KS]) + lgeo;
        const uint32_t Vb = smem_u32(&Vs[(jt&1)*AT_KS]) + lgeo;

        // ---- mma1: S = Q . K'^T ----
        float sacc[8][4];
        #pragma unroll
        for (int i=0;i<8;i++){ sacc[i][0]=0.f;sacc[i][1]=0.f;sacc[i][2]=0.f;sacc[i][3]=0.f; }
        #pragma unroll
        for (int kc=0; kc<4; kc++){
            #pragma unroll
            for (int np=0; np<4; np++){          // n16 groups over j64
                uint32_t b[4];
                ldm4(b, Kb + (uint32_t)(np*16*(APH*2) + kc*32));
                mma16(sacc[2*np],   Qf[kc], b[0], b[2]);
                mma16(sacc[2*np+1], Qf[kc], b[1], b[3]);
            }
        }

        // ---- SELU (f32) + direct pack into f16 A-fragments ----
        uint32_t amf[4][4];
        #pragma unroll
        for (int f=0; f<8; f++)
            #pragma unroll
            for (int r=0; r<4; r++){
                float v = sacc[f][r];
                sacc[f][r] = (v > 0.f) ? LAM * v : AL * (__expf(v) - 1.f);
            }
        #pragma unroll
        for (int jc=0; jc<4; jc++){
            amf[jc][0] = h2pack(sacc[2*jc][0],   sacc[2*jc][1]);
            amf[jc][1] = h2pack(sacc[2*jc][2],   sacc[2*jc][3]);
            amf[jc][2] = h2pack(sacc[2*jc+1][0], sacc[2*jc+1][1]);
            amf[jc][3] = h2pack(sacc[2*jc+1][2], sacc[2*jc+1][3]);
        }

        // ---- mma2: O += attn . V^T ----
        #pragma unroll
        for (int jc=0; jc<4; jc++){              // k16 = j16 chunks
            #pragma unroll
            for (int np=0; np<4; np++){          // n16 groups over d64
                uint32_t b[4];
                ldm4(b, Vb + (uint32_t)(np*16*(APH*2) + jc*32));
                mma16(oacc[2*np],   amf[jc], b[0], b[2]);
                mma16(oacc[2*np+1], amf[jc], b[1], b[3]);
            }
        }

        if (jt+1 < 32){ CP_WAIT0(); __syncthreads(); }
    }

    // ---- store O * S^-1/2 ----
    const float OS = 0.022097086912079612f;   // 1/sqrt(2048)
    const int g = lane >> 2, q2 = lane & 3;
    #pragma unroll
    for (int dt=0; dt<8; dt++){
        const int d = dt*8 + 2*q2;
        #pragma unroll
        for (int half_=0; half_<2; half_++){
            const int irow = i0 + wid*16 + g + half_*8;
            float2 o;
            o.x = oacc[dt][half_*2+0] * OS;
            o.y = oacc[dt][half_*2+1] * OS;
            *(float2*)(out + ((size_t)(bb*S_ + irow))*D_ + h*DH_ + d) = o;
        }
    }
}

// ---------------------------------------------------------------------------
extern "C" void kernel_launch(void* const* d_in, const int* in_sizes, int n_in,
                              void* d_out, int out_size) {
    const float* x    = (const float*)d_in[0];
    const float* W    = (const float*)d_in[1];
    const float* bias = (const float*)d_in[2];
    float* out = (float*)d_out;

    cudaFuncSetAttribute(proj_kernel, cudaFuncAttributeMaxDynamicSharedMemorySize, PJ_SMEM);
    cudaFuncSetAttribute(attn_kernel, cudaFuncAttributeMaxDynamicSharedMemorySize, AT_SMEM);

    vt_kernel<<<dim3(32, 64), 256>>>(x);

    dim3 g1(16, 64);    // N tiles x M tiles
    proj_kernel<<<g1, 256, PJ_SMEM>>>(x, W, bias);

    ksum_kernel<<<dim3(8, 64), 256>>>();
    ksub_kernel<<<dim3(8, 64), 256>>>();

    dim3 g3(16, 64);    // i tiles x (b*h)
    attn_kernel<<<g3, 256, AT_SMEM>>>(out);
}